// round 11
// baseline (speedup 1.0000x reference)
#include <cuda_runtime.h>
#include <cuda_fp16.h>
#include <math.h>
#include <stdint.h>

#define NT 4000
#define NS 5000
#define LOG2E 1.4426950408889634f
typedef unsigned short u16;

// ===================== scratch =============================================
__device__ __align__(16) u16 g_A0f[16000000];
__device__ __align__(16) u16 g_A1f[20000000];
__device__ __align__(16) u16 g_A2f[25000000];
__device__ __align__(16) u16 g_Es[25000000];
__device__ __align__(16) u16 g_Ev[20000000];
__device__ __align__(16) u16 g_Et[16000000];
__device__ __align__(16) u16 g_Xf[2432000];
__device__ float g_src_inv[NS];
__device__ float g_vna_inv[NT];
__device__ float g_tgt_inv[NT];
__device__ __align__(16) float g_lr[3 * NS * 128];
__device__ __align__(16) float g_semb[3 * NT * 128];
__device__ __align__(16) float g_Y[6200000];
__device__ __align__(16) float g_xt[NT * 128];

// ===================== PTX helpers =========================================
__device__ __forceinline__ uint32_t smem_u32(const void* p) {
    uint32_t a;
    asm("{ .reg .u64 t; cvta.to.shared.u64 t, %1; cvt.u32.u64 %0, t; }" : "=r"(a) : "l"(p));
    return a;
}
#define CP_ASYNC16(saddr, gaddr, sz) \
    asm volatile("cp.async.ca.shared.global [%0], [%1], 16, %2;" :: "r"(saddr), "l"(gaddr), "r"(sz))
#define CP_COMMIT() asm volatile("cp.async.commit_group;" ::: "memory")
#define CP_WAIT2()  asm volatile("cp.async.wait_group 2;" ::: "memory")
#define LDSM4(r, a) \
    asm volatile("ldmatrix.sync.aligned.m8n8.x4.shared.b16 {%0,%1,%2,%3}, [%4];" \
        : "=r"((r)[0]), "=r"((r)[1]), "=r"((r)[2]), "=r"((r)[3]) : "r"(a))
#define MMA_FP16(c, A, b0, b1) \
    asm volatile("mma.sync.aligned.m16n8k16.row.col.f32.f16.f16.f32 " \
        "{%0,%1,%2,%3},{%4,%5,%6,%7},{%8,%9},{%0,%1,%2,%3};" \
        : "+f"((c)[0]), "+f"((c)[1]), "+f"((c)[2]), "+f"((c)[3]) \
        : "r"((A)[0]), "r"((A)[1]), "r"((A)[2]), "r"((A)[3]), "r"(b0), "r"(b1))

__device__ __forceinline__ uint32_t pack_h2(float a, float b) {
    return (uint32_t)__half_as_ushort(__float2half_rn(a)) |
           ((uint32_t)__half_as_ushort(__float2half_rn(b)) << 16);
}
__device__ __forceinline__ uint4 pack8(const float* v) {
    uint4 H;
    H.x = pack_h2(v[0], v[1]); H.y = pack_h2(v[2], v[3]);
    H.z = pack_h2(v[4], v[5]); H.w = pack_h2(v[6], v[7]);
    return H;
}
__device__ __forceinline__ uint32_t swz(uint32_t x) { return x ^ ((x >> 3) & 0x70); }

// ===================== small kernels ========================================
__global__ void unpack_kernel(const float* __restrict__ xp, float* __restrict__ out, int n) {
    int i = blockIdx.x * blockDim.x + threadIdx.x;
    if (i >= n * 128) return;
    int r = i >> 7, c = i & 127, b = c >> 6, d = c & 63;
    out[((size_t)b * n + r) * 64 + d] = xp[i];
}
__global__ void tofp16_kernel(const float* __restrict__ A, u16* __restrict__ F, int n4) {
    int i = blockIdx.x * blockDim.x + threadIdx.x;
    if (i >= n4) return;
    float4 v = ((const float4*)A)[i];
    uint2 o;
    o.x = pack_h2(v.x * 4096.f, v.y * 4096.f);
    o.y = pack_h2(v.z * 4096.f, v.w * 4096.f);
    ((uint2*)F)[i] = o;
}
__global__ __launch_bounds__(256)
void pack_prep(const float* __restrict__ x, float* __restrict__ xp,
               u16* __restrict__ Xf, int n)
{
    __shared__ float t[8][128];
    const int tid = threadIdx.x, r0 = blockIdx.x * 8;
    for (int i = tid; i < 1024; i += 256) {
        int r = i >> 7, c = i & 127, b = c >> 6, d = c & 63;
        float v = x[((size_t)b * n + r0 + r) * 64 + d];
        xp[(size_t)(r0 + r) * 128 + c] = v;
        t[r][c] = v;
    }
    __syncthreads();
    if (tid < 128) {
        float v[8];
#pragma unroll
        for (int j = 0; j < 8; j++) v[j] = t[j][tid];
        *(uint4*)(Xf + (size_t)tid * n + r0) = pack8(v);
    }
}

// ===================== fused adaptive adjacency =============================
__global__ __launch_bounds__(256)
void adp_fused(const float* __restrict__ nv1, const float* __restrict__ nv2,
               u16* __restrict__ E, float* __restrict__ inv, int ncols)
{
    extern __shared__ float ds[];
    __shared__ float v1s[4][30];
    __shared__ float red[8][4];
    __shared__ float Mrow[4];
    const int tid = threadIdx.x, r0 = blockIdx.x * 4;
    const int lane = tid & 31, wrp = tid >> 5;
    if (tid < 120) v1s[tid / 30][tid % 30] = nv1[(size_t)(r0 + tid / 30) * 30 + tid % 30];
    __syncthreads();

    float mx[4];
#pragma unroll
    for (int r = 0; r < 4; r++) mx[r] = 0.f;
    for (int c = tid; c < ncols; c += 256) {
        float col[30];
#pragma unroll
        for (int q = 0; q < 30; q++) col[q] = nv2[(size_t)q * ncols + c];
#pragma unroll
        for (int r = 0; r < 4; r++) {
            float dot = 0.f;
#pragma unroll
            for (int q = 0; q < 30; q++) dot = fmaf(v1s[r][q], col[q], dot);
            float dp = fmaxf(dot, 0.f);
            ds[r * ncols + c] = dp;
            mx[r] = fmaxf(mx[r], dp);
        }
    }
#pragma unroll
    for (int r = 0; r < 4; r++) {
        float v = mx[r];
#pragma unroll
        for (int off = 16; off > 0; off >>= 1)
            v = fmaxf(v, __shfl_down_sync(0xffffffffu, v, off));
        if (lane == 0) red[wrp][r] = v;
    }
    __syncthreads();
    if (tid < 4) {
        float v = red[0][tid];
#pragma unroll
        for (int w = 1; w < 8; w++) v = fmaxf(v, red[w][tid]);
        Mrow[tid] = v;
    }
    __syncthreads();

    float M[4], ps[4];
#pragma unroll
    for (int r = 0; r < 4; r++) { M[r] = Mrow[r]; ps[r] = 0.f; }
    for (int c = tid * 2; c < ncols; c += 512) {
#pragma unroll
        for (int r = 0; r < 4; r++) {
            size_t idx = (size_t)(r0 + r) * ncols + c;
            float t0 = (ds[r * ncols + c]     - M[r]) * LOG2E;
            float t1 = (ds[r * ncols + c + 1] - M[r]) * LOG2E;
            __half2 tin = __floats2half2_rn(t0, t1);
            uint32_t ti = *(uint32_t*)&tin, eo;
            asm("ex2.approx.f16x2 %0, %1;" : "=r"(eo) : "r"(ti));
            *(uint32_t*)(E + idx) = eo;
            float2 ef = __half22float2(*(__half2*)&eo);
            ps[r] += ef.x + ef.y;
        }
    }
#pragma unroll
    for (int r = 0; r < 4; r++) {
        float v = ps[r];
#pragma unroll
        for (int off = 16; off > 0; off >>= 1) v += __shfl_down_sync(0xffffffffu, v, off);
        if (lane == 0) red[wrp][r] = v;
    }
    __syncthreads();
    if (tid < 4) {
        float s = 0.f;
#pragma unroll
        for (int w = 0; w < 8; w++) s += red[w][tid];
        inv[r0 + tid] = 1.0f / s;
    }
}

// ===================== merged-support split-K HMMA GEMM =====================
// CTA = 64 rows x 64 cols, 256 thr (8 warps 4m x 2n), both supports,
// 4-stage cp.async, load 2-ahead, ONE sync per k-iter.
#define GKT 64
#define STG 24576          // Ad 8K | Ae 8K | B 8K
#define SMEM_GEMM (4 * STG)

__device__ __forceinline__ void stage_ldm(uint32_t sdst,
    const u16* __restrict__ Ad, const u16* __restrict__ Ae, const u16* __restrict__ B,
    int row0, int kbase, int n, int kend, int m, int tid)
{
#pragma unroll
    for (int t = 0; t < 2; t++) {
        int id = tid + t * 256;
        int r = id >> 3, kc = id & 7;
        int gr = row0 + r, gk = kbase + kc * 8;
        bool v = (gr < n) && (gk < kend);
        size_t gi = (size_t)(v ? gr : 0) * m + (v ? gk : 0);
        uint32_t sw = swz(r * 128 + kc * 16);
        unsigned sz = v ? 16u : 0u;
        CP_ASYNC16(sdst + sw, Ad + gi, sz);
        CP_ASYNC16(sdst + 8192 + sw, Ae + gi, sz);
    }
#pragma unroll
    for (int t = 0; t < 2; t++) {
        int id = tid + t * 256;
        int cr = id >> 3, kc = id & 7;
        int gk = kbase + kc * 8;
        bool v = (gk < kend);
        size_t gi = (size_t)cr * m + (v ? gk : 0);
        uint32_t sw = swz(cr * 128 + kc * 16);
        CP_ASYNC16(sdst + 16384 + sw, B + gi, v ? 16u : 0u);
    }
}

__global__ __launch_bounds__(256, 2)
void hmma_gemm3m(const u16* __restrict__ Af, const u16* __restrict__ Ef,
                 const float* __restrict__ invsum,
                 const u16* __restrict__ Xf,
                 float* __restrict__ Y, int n, int m, int mh, int ny)
{
    extern __shared__ __align__(128) char smem[];
    const uint32_t sb = smem_u32(smem);
    const int tid = threadIdx.x, lane = tid & 31, wid = tid >> 5;
    const int wm = wid >> 1, wn = wid & 1;
    const int tile = blockIdx.x >> 1, nh = blockIdx.x & 1;
    const int row0 = tile * 64, col0 = nh * 64;
    const int yb = blockIdx.y % ny, zs = blockIdx.y / ny;
    const u16* __restrict__ B = Xf + ((size_t)yb * 128 + col0) * m;
    const int k0 = zs * mh, kend = min(m, k0 + mh);
    const int ktn = (kend - k0 + GKT - 1) / GKT;

    float accD[4][4], accE[4][4];
#pragma unroll
    for (int j = 0; j < 4; j++)
#pragma unroll
        for (int q = 0; q < 4; q++) { accD[j][q] = 0.f; accE[j][q] = 0.f; }

    uint32_t arow, axor;
    { int r = wm * 16 + (lane & 7) + (((lane >> 3) & 1) << 3);
      arow = (uint32_t)r * 128; axor = ((uint32_t)r * 16) & 0x70; }
    const uint32_t akbs = ((lane >> 4) & 1) * 16;
    uint32_t brow[2], bxor[2];
#pragma unroll
    for (int bt = 0; bt < 2; bt++) {
        int r = wn * 32 + bt * 16 + (lane & 7) + (((lane >> 4) & 1) << 3);
        brow[bt] = (uint32_t)r * 128; bxor[bt] = ((uint32_t)r * 16) & 0x70;
    }
    const uint32_t bkbs = ((lane >> 3) & 1) * 16;

    stage_ldm(sb, Af, Ef, B, row0, k0, n, kend, m, tid);
    CP_COMMIT();
    if (1 < ktn) stage_ldm(sb + STG, Af, Ef, B, row0, k0 + GKT, n, kend, m, tid);
    CP_COMMIT();

    for (int kt = 0; kt < ktn; kt++) {
        if (kt + 2 < ktn)
            stage_ldm(sb + ((kt + 2) & 3) * STG, Af, Ef, B,
                      row0, k0 + (kt + 2) * GKT, n, kend, m, tid);
        CP_COMMIT();
        CP_WAIT2();
        __syncthreads();
        const uint32_t stb = sb + (kt & 3) * STG;
#pragma unroll
        for (int ks = 0; ks < 4; ks++) {
            const uint32_t kb = ks * 32;
            uint32_t fad[4], fae[4], fb[2][4];
            LDSM4(fad, stb + arow + ((kb + akbs) ^ axor));
            LDSM4(fae, stb + 8192 + arow + ((kb + akbs) ^ axor));
#pragma unroll
            for (int bt = 0; bt < 2; bt++)
                LDSM4(fb[bt], stb + 16384 + brow[bt] + ((kb + bkbs) ^ bxor[bt]));
#pragma unroll
            for (int nt = 0; nt < 4; nt++) {
                const int g = nt >> 1, h = (nt & 1) << 1;
                MMA_FP16(accD[nt], fad, fb[g][h], fb[g][h + 1]);
                MMA_FP16(accE[nt], fae, fb[g][h], fb[g][h + 1]);
            }
        }
    }

    float* __restrict__ Yd = Y + (size_t)(zs * 2 * ny + yb * 2) * n * 128;
    float* __restrict__ Ye = Yd + (size_t)n * 128;
    const int gr0 = row0 + wm * 16 + (lane >> 2), gr1 = gr0 + 8;
    const float SD = 2.44140625e-4f;
    const float e0 = (gr0 < n) ? invsum[gr0] : 0.f;
    const float e1 = (gr1 < n) ? invsum[gr1] : 0.f;
#pragma unroll
    for (int nt = 0; nt < 4; nt++) {
        int col = col0 + wn * 32 + nt * 8 + ((lane & 3) << 1);
        if (gr0 < n) {
            *(float2*)(Yd + (size_t)gr0 * 128 + col) =
                make_float2(accD[nt][0] * SD, accD[nt][1] * SD);
            *(float2*)(Ye + (size_t)gr0 * 128 + col) =
                make_float2(accE[nt][0] * e0, accE[nt][1] * e0);
        }
        if (gr1 < n) {
            *(float2*)(Yd + (size_t)gr1 * 128 + col) =
                make_float2(accD[nt][2] * SD, accD[nt][3] * SD);
            *(float2*)(Ye + (size_t)gr1 * 128 + col) =
                make_float2(accE[nt][2] * e1, accE[nt][3] * e1);
        }
    }
}

// ===================== source epilogue ======================================
__global__ __launch_bounds__(256)
void epi_src(const float* __restrict__ Y, const float* __restrict__ W,
             const float* __restrict__ bias, const float* __restrict__ prev,
             float* __restrict__ out, u16* __restrict__ Xf, int n, size_t ps, int nz)
{
    __shared__ float Ws[128][64];
    __shared__ float Y1s[8][128];
    __shared__ float Y2s[8][128];
    __shared__ float oS[8][128];
    const int tid = threadIdx.x, r0 = blockIdx.x * 8;
    for (int i = tid; i < 8192; i += 256) Ws[i >> 6][i & 63] = W[i];
    const float* __restrict__ Y2 = Y + (size_t)n * 128;
    for (int i = tid; i < 1024; i += 256) {
        int r = i >> 7, c = i & 127;
        size_t gi = (size_t)(r0 + r) * 128 + c;
        float s1 = 0.f, s2 = 0.f;
        for (int q = 0; q < nz; q++) { s1 += Y[gi + q * ps]; s2 += Y2[gi + q * ps]; }
        Y1s[r][c] = s1; Y2s[r][c] = s2;
    }
    __syncthreads();
    const int c = tid & 127, rg = tid >> 7, d = c & 63, b64 = c & 64;
    const float bv = bias[d];
    for (int rr = rg; rr < 8; rr += 2) {
        float acc = bv;
#pragma unroll
        for (int k = 0; k < 64; k++) {
            acc = fmaf(Y1s[rr][b64 + k], Ws[k][d], acc);
            acc = fmaf(Y2s[rr][b64 + k], Ws[64 + k][d], acc);
        }
        float g = prev[(size_t)(r0 + rr) * 128 + c] + fmaxf(acc, 0.f);
        out[(size_t)(r0 + rr) * 128 + c] = g;
        oS[rr][c] = g;
    }
    __syncthreads();
    if (tid < 128) {
        float v[8];
#pragma unroll
        for (int j = 0; j < 8; j++) v[j] = oS[j][tid];
        *(uint4*)(Xf + (size_t)tid * n + r0) = pack8(v);
    }
}

// ===================== VNA epilogue =========================================
__global__ __launch_bounds__(256)
void epi_vna(const float* __restrict__ Y, const float* __restrict__ W,
             const float* __restrict__ bias, float* __restrict__ semb,
             int n, size_t ps, int nz)
{
    __shared__ float Ws[128][64];
    __shared__ float Y1s[8][128];
    __shared__ float Y2s[8][128];
    const int tid = threadIdx.x, r0 = blockIdx.x * 8, y = blockIdx.y;
    const float* __restrict__ Wp = W + y * 8192;
    const float* __restrict__ Y1 = Y + (size_t)(2 * y) * n * 128;
    const float* __restrict__ Y2 = Y1 + (size_t)n * 128;
    float* __restrict__ out = semb + (size_t)y * n * 128;
    for (int i = tid; i < 8192; i += 256) Ws[i >> 6][i & 63] = Wp[i];
    for (int i = tid; i < 1024; i += 256) {
        int r = i >> 7, c = i & 127;
        size_t gi = (size_t)(r0 + r) * 128 + c;
        float s1 = 0.f, s2 = 0.f;
        for (int q = 0; q < nz; q++) { s1 += Y1[gi + q * ps]; s2 += Y2[gi + q * ps]; }
        Y1s[r][c] = s1; Y2s[r][c] = s2;
    }
    __syncthreads();
    const int c = tid & 127, rg = tid >> 7, d = c & 63, b64 = c & 64;
    const float bv = bias[y * 64 + d];
    for (int rr = rg; rr < 8; rr += 2) {
        float acc = bv;
#pragma unroll
        for (int k = 0; k < 64; k++) {
            acc = fmaf(Y1s[rr][b64 + k], Ws[k][d], acc);
            acc = fmaf(Y2s[rr][b64 + k], Ws[64 + k][d], acc);
        }
        out[(size_t)(r0 + rr) * 128 + c] = fmaxf(acc, 0.f);
    }
}

// ===================== target epilogue + gated fusion =======================
#define SMEM_TGT 49152
__global__ __launch_bounds__(256)
void epi_tgt(const float* __restrict__ Y, const float* __restrict__ W,
             const float* __restrict__ bias, const float* __restrict__ S,
             const float* __restrict__ fWt, const float* __restrict__ fWs,
             const float* __restrict__ fb, float* __restrict__ xt,
             u16* __restrict__ Xf, int n, size_t ps, int nz)
{
    extern __shared__ __align__(16) char dsm[];
    float* Wbuf = (float*)dsm;
    float (*Y1s)[128] = (float(*)[128])(dsm + 32768);
    float (*Y2s)[128] = (float(*)[128])(dsm + 36864);
    float (*tS)[128]  = (float(*)[128])(dsm + 40960);
    float (*sS)[128]  = (float(*)[128])(dsm + 45056);
    const int tid = threadIdx.x, r0 = blockIdx.x * 8;
    for (int i = tid; i < 8192; i += 256) Wbuf[i] = W[i];
    const float* __restrict__ Y2 = Y + (size_t)n * 128;
    for (int i = tid; i < 1024; i += 256) {
        int r = i >> 7, c = i & 127;
        size_t gi = (size_t)(r0 + r) * 128 + c;
        float s1 = 0.f, s2 = 0.f;
        for (int q = 0; q < nz; q++) { s1 += Y[gi + q * ps]; s2 += Y2[gi + q * ps]; }
        Y1s[r][c] = s1; Y2s[r][c] = s2;
        sS[r][c] = S[gi];
    }
    __syncthreads();
    const int c = tid & 127, rg = tid >> 7, d = c & 63, b64 = c & 64;
    const float bv = bias[d];
    for (int rr = rg; rr < 8; rr += 2) {
        float acc = bv;
#pragma unroll
        for (int k = 0; k < 64; k++) {
            acc = fmaf(Y1s[rr][b64 + k], Wbuf[k * 64 + d], acc);
            acc = fmaf(Y2s[rr][b64 + k], Wbuf[(64 + k) * 64 + d], acc);
        }
        tS[rr][c] = fmaxf(acc, 0.f);
    }
    __syncthreads();
    for (int i = tid; i < 4096; i += 256) { Wbuf[i] = fWt[i]; Wbuf[4096 + i] = fWs[i]; }
    __syncthreads();
    const float fbv = fb[d];
    for (int rr = rg; rr < 8; rr += 2) {
        float za = fbv;
#pragma unroll
        for (int k = 0; k < 64; k++) {
            za = fmaf(tS[rr][b64 + k], Wbuf[k * 64 + d], za);
            za = fmaf(sS[rr][b64 + k], Wbuf[4096 + k * 64 + d], za);
        }
        float z = 1.f / (1.f + expf(-za));
        float tv = tS[rr][c], sv = sS[rr][c];
        size_t gi = (size_t)(r0 + rr) * 128 + c;
        float nx = xt[gi] + z * tv + (1.f - z) * sv;
        xt[gi] = nx;
        Y1s[rr][c] = nx;
    }
    __syncthreads();
    if (Xf && tid < 128) {
        float v[8];
#pragma unroll
        for (int j = 0; j < 8; j++) v[j] = Y1s[j][tid];
        *(uint4*)(Xf + (size_t)tid * n + r0) = pack8(v);
    }
}

// ===================== launcher =============================================
extern "C" void kernel_launch(void* const* d_in, const int* in_sizes, int n_in,
                              void* d_out, int out_size)
{
    (void)in_sizes; (void)n_in; (void)out_size;
    const float* A0      = (const float*)d_in[0];
    const float* A1      = (const float*)d_in[1];
    const float* A2      = (const float*)d_in[2];
    const float* x0      = (const float*)d_in[3];
    const float* x1      = (const float*)d_in[4];
    const float* src_nv1 = (const float*)d_in[5];
    const float* src_nv2 = (const float*)d_in[6];
    const float* src_W   = (const float*)d_in[7];
    const float* src_b   = (const float*)d_in[8];
    const float* vna_nv1 = (const float*)d_in[9];
    const float* vna_nv2 = (const float*)d_in[10];
    const float* vna_W   = (const float*)d_in[11];
    const float* vna_b   = (const float*)d_in[12];
    const float* tgt_nv1 = (const float*)d_in[13];
    const float* tgt_nv2 = (const float*)d_in[14];
    const float* tgt_W   = (const float*)d_in[15];
    const float* tgt_b   = (const float*)d_in[16];
    const float* fus_Wt  = (const float*)d_in[17];
    const float* fus_Ws  = (const float*)d_in[18];
    const float* fus_b   = (const float*)d_in[19];

    u16 *A0f, *A1f, *A2f, *Es, *Ev, *Et, *Xf;
    float *src_inv, *vna_inv, *tgt_inv, *lr, *semb, *Yb, *xtb;
    cudaGetSymbolAddress((void**)&A0f, g_A0f);
    cudaGetSymbolAddress((void**)&A1f, g_A1f);
    cudaGetSymbolAddress((void**)&A2f, g_A2f);
    cudaGetSymbolAddress((void**)&Es, g_Es);
    cudaGetSymbolAddress((void**)&Ev, g_Ev);
    cudaGetSymbolAddress((void**)&Et, g_Et);
    cudaGetSymbolAddress((void**)&Xf, g_Xf);
    cudaGetSymbolAddress((void**)&src_inv, g_src_inv);
    cudaGetSymbolAddress((void**)&vna_inv, g_vna_inv);
    cudaGetSymbolAddress((void**)&tgt_inv, g_tgt_inv);
    cudaGetSymbolAddress((void**)&lr, g_lr);
    cudaGetSymbolAddress((void**)&semb, g_semb);
    cudaGetSymbolAddress((void**)&Yb, g_Y);
    cudaGetSymbolAddress((void**)&xtb, g_xt);

    cudaFuncSetAttribute(hmma_gemm3m, cudaFuncAttributeMaxDynamicSharedMemorySize, SMEM_GEMM);
    cudaFuncSetAttribute(epi_tgt, cudaFuncAttributeMaxDynamicSharedMemorySize, SMEM_TGT);
    cudaFuncSetAttribute(adp_fused, cudaFuncAttributeMaxDynamicSharedMemorySize, 4 * NS * 4);

    const size_t SLOT = (size_t)128 * NS;
    u16* Xf3 = Xf + 3 * SLOT;
    const int xS = ((NS + 63) / 64) * 2;   // 158
    const int xT = ((NT + 63) / 64) * 2;   // 126
    const int mhS = 2560, mhT = 1024;      // K-split chunk (mult of 64)
    const size_t psS = (size_t)2 * NS * 128;
    const size_t psT1 = (size_t)2 * NT * 128;
    const size_t psT3 = (size_t)6 * NT * 128;

    // ---- src chain first (profiled launch idx 3 = first src GEMM) ----
    pack_prep<<<NS / 8, 256>>>(x1, lr, Xf, NS);
    tofp16_kernel<<<(NS * NS / 4 + 255) / 256, 256>>>(A2, A2f, NS * NS / 4);
    adp_fused<<<NS / 4, 256, 4 * NS * 4>>>(src_nv1, src_nv2, Es, src_inv, NS);
    for (int i = 0; i < 2; i++) {
        hmma_gemm3m<<<dim3(xS, 2), 256, SMEM_GEMM>>>(A2f, Es, src_inv,
            Xf + i * SLOT, Yb, NS, NS, mhS, 1);
        epi_src<<<NS / 8, 256>>>(Yb, src_W + i * 8192, src_b + i * 64,
            lr + (size_t)i * NS * 128, lr + (size_t)(i + 1) * NS * 128,
            Xf + (i + 1) * SLOT, NS, psS, 2);
    }

    // ---- rest of prep ----
    pack_prep<<<NT / 8, 256>>>(x0, xtb, Xf3, NT);
    tofp16_kernel<<<(NT * NT / 4 + 255) / 256, 256>>>(A0, A0f, NT * NT / 4);
    tofp16_kernel<<<(NT * NS / 4 + 255) / 256, 256>>>(A1, A1f, NT * NS / 4);
    adp_fused<<<NT / 4, 256, 4 * NS * 4>>>(vna_nv1, vna_nv2, Ev, vna_inv, NS);
    adp_fused<<<NT / 4, 256, 4 * NT * 4>>>(tgt_nv1, tgt_nv2, Et, tgt_inv, NT);

    // ---- VNA block: 3 layers batched, K-split 2 ----
    hmma_gemm3m<<<dim3(xT, 6), 256, SMEM_GEMM>>>(A1f, Ev, vna_inv, Xf, Yb, NT, NS, mhS, 3);
    epi_vna<<<dim3(NT / 8, 3), 256>>>(Yb, vna_W, vna_b, semb, NT, psT3, 2);

    // ---- Target GC block with gated fusion, K-split 4 ----
    for (int i = 0; i < 3; i++) {
        hmma_gemm3m<<<dim3(xT, 4), 256, SMEM_GEMM>>>(A0f, Et, tgt_inv, Xf3, Yb, NT, NT, mhT, 1);
        epi_tgt<<<NT / 8, 256, SMEM_TGT>>>(Yb, tgt_W + i * 8192, tgt_b + i * 64,
            semb + (size_t)i * NT * 128, fus_Wt + i * 4096, fus_Ws + i * 4096,
            fus_b + i * 64, xtb, (i < 2) ? Xf3 : (u16*)nullptr, NT, psT1, 4);
    }

    unpack_kernel<<<(NT * 128 + 255) / 256, 256>>>(xtb, (float*)d_out, NT);
}